// round 13
// baseline (speedup 1.0000x reference)
#include <cuda_runtime.h>
#include <math.h>
#include <stdint.h>

#define DM 768
#define NH 12
#define DK 64
#define SMAX 4096

__device__ float g_Q[SMAX * DM];
__device__ float g_K[SMAX * DM];
__device__ float g_V[SMAX * DM];
__device__ float g_C[SMAX * DM];
// Split-KV partial buffers (half A / half B), rows >= SMAX/2 used.
__device__ float g_PA[SMAX * DM];
__device__ float g_PB[SMAX * DM];
__device__ float g_MA[NH * SMAX], g_LA[NH * SMAX];
__device__ float g_MB[NH * SMAX], g_LB[NH * SMAX];

__device__ __forceinline__ uint32_t f2tf32(float f) {
    uint32_t r;
    asm("cvt.rna.tf32.f32 %0, %1;" : "=r"(r) : "f"(f));
    return r;
}

__device__ __forceinline__ uint32_t smem_u32(const void* p) {
    uint32_t a;
    asm("{ .reg .u64 t; cvta.to.shared.u64 t, %1; cvt.u32.u64 %0, t; }"
        : "=r"(a) : "l"(p));
    return a;
}

__device__ __forceinline__ void cp_async16(uint32_t smem_addr, const void* gptr) {
    asm volatile("cp.async.ca.shared.global [%0], [%1], 16;"
                 :: "r"(smem_addr), "l"(gptr));
}
__device__ __forceinline__ void cp_commit() {
    asm volatile("cp.async.commit_group;");
}
template <int N>
__device__ __forceinline__ void cp_wait() {
    asm volatile("cp.async.wait_group %0;" :: "n"(N));
}

__device__ __forceinline__ void mma_tf32(float* d, const uint32_t* a, const uint32_t* b) {
    asm volatile(
        "mma.sync.aligned.m16n8k8.row.col.f32.tf32.tf32.f32 "
        "{%0,%1,%2,%3}, {%4,%5,%6,%7}, {%8,%9}, {%0,%1,%2,%3};"
        : "+f"(d[0]), "+f"(d[1]), "+f"(d[2]), "+f"(d[3])
        : "r"(a[0]), "r"(a[1]), "r"(a[2]), "r"(a[3]), "r"(b[0]), "r"(b[1]));
}

// ---------------------------------------------------------------------------
// GEMM (BM=128, for QKV): 2x-tf32, BK=32, cp.async double buffer.
// ---------------------------------------------------------------------------
#define BM 128
#define BN 128
#define GBK 32
#define GAST 36
#define GBST 136
#define GEMM_SMEM ((2 * BM * GAST + 2 * GBK * GBST) * 4)

__device__ __forceinline__ void gemm_core(
    const float* __restrict__ A, const float* __restrict__ W,
    const float* __restrict__ bias, float* __restrict__ C,
    int m0, int n0) {
    extern __shared__ float gsm[];
    float* AsF = gsm;
    float* BsF = gsm + 2 * BM * GAST;

    const int tid = threadIdx.x;
    const int wid = tid >> 5;
    const int lane = tid & 31;
    const int g = lane >> 2;
    const int tg = lane & 3;
    const int wm = (wid & 1) * 64;
    const int wn = (wid >> 1) * 32;

    const uint32_t sA0 = smem_u32(AsF);
    const uint32_t sA1 = smem_u32(AsF + BM * GAST);
    const uint32_t sB0 = smem_u32(BsF);
    const uint32_t sB1 = smem_u32(BsF + GBK * GBST);

    float acc[4][4][4] = {};

    auto load_tile = [&](int ki, int st) {
        uint32_t sa = st ? sA1 : sA0;
        uint32_t sb = st ? sB1 : sB0;
        const int k0 = ki * GBK;
        #pragma unroll
        for (int j = 0; j < 4; ++j) {
            int s = tid + j * 256;
            int ra = s >> 3, ca = (s & 7) * 4;
            cp_async16(sa + (ra * GAST + ca) * 4,
                       &A[(size_t)(m0 + ra) * DM + k0 + ca]);
        }
        #pragma unroll
        for (int j = 0; j < 4; ++j) {
            int s = tid + j * 256;
            int rb = s >> 5, cb = (s & 31) * 4;
            cp_async16(sb + (rb * GBST + cb) * 4,
                       &W[(size_t)(k0 + rb) * DM + n0 + cb]);
        }
        cp_commit();
    };

    load_tile(0, 0);

    const int NIT = DM / GBK;  // 24
    for (int ki = 0; ki < NIT; ++ki) {
        const int st = ki & 1;
        cp_wait<0>();
        __syncthreads();
        if (ki + 1 < NIT) load_tile(ki + 1, st ^ 1);

        const float* Af = AsF + st * BM * GAST;
        const float* Bf = BsF + st * GBK * GBST;

        #pragma unroll
        for (int ks = 0; ks < GBK; ks += 8) {
            uint32_t af[4][4], bfh[4][2], bfl[4][2];
            #pragma unroll
            for (int mt = 0; mt < 4; ++mt) {
                int rb = wm + mt * 16;
                af[mt][0] = f2tf32(Af[(rb + g) * GAST + ks + tg]);
                af[mt][1] = f2tf32(Af[(rb + g + 8) * GAST + ks + tg]);
                af[mt][2] = f2tf32(Af[(rb + g) * GAST + ks + tg + 4]);
                af[mt][3] = f2tf32(Af[(rb + g + 8) * GAST + ks + tg + 4]);
            }
            #pragma unroll
            for (int nt = 0; nt < 4; ++nt) {
                int cb = wn + nt * 8;
                float b0 = Bf[(ks + tg) * GBST + cb + g];
                float b1 = Bf[(ks + tg + 4) * GBST + cb + g];
                bfh[nt][0] = f2tf32(b0);
                bfh[nt][1] = f2tf32(b1);
                bfl[nt][0] = f2tf32(b0 - __uint_as_float(bfh[nt][0]));
                bfl[nt][1] = f2tf32(b1 - __uint_as_float(bfh[nt][1]));
            }
            #pragma unroll
            for (int mt = 0; mt < 4; ++mt)
                #pragma unroll
                for (int nt = 0; nt < 4; ++nt)
                    mma_tf32(acc[mt][nt], af[mt], bfl[nt]);
            #pragma unroll
            for (int mt = 0; mt < 4; ++mt)
                #pragma unroll
                for (int nt = 0; nt < 4; ++nt)
                    mma_tf32(acc[mt][nt], af[mt], bfh[nt]);
        }
    }

    #pragma unroll
    for (int mt = 0; mt < 4; ++mt) {
        int row = m0 + wm + mt * 16 + g;
        #pragma unroll
        for (int nt = 0; nt < 4; ++nt) {
            int col = n0 + wn + nt * 8 + tg * 2;
            float b0 = bias[col], b1 = bias[col + 1];
            float2 v0 = make_float2(acc[mt][nt][0] + b0, acc[mt][nt][1] + b1);
            float2 v1 = make_float2(acc[mt][nt][2] + b0, acc[mt][nt][3] + b1);
            *reinterpret_cast<float2*>(&C[(size_t)row * DM + col]) = v0;
            *reinterpret_cast<float2*>(&C[(size_t)(row + 8) * DM + col]) = v1;
        }
    }
}

__global__ __launch_bounds__(256) void gemm_qkv_kernel(
    const float* A0, const float* A1, const float* A2,
    const float* W0, const float* W1, const float* W2,
    const float* b0, const float* b1, const float* b2,
    float* C0, float* C1, float* C2) {
    const int z = blockIdx.z;
    const float* A = (z == 0) ? A0 : (z == 1) ? A1 : A2;
    const float* W = (z == 0) ? W0 : (z == 1) ? W1 : W2;
    const float* b = (z == 0) ? b0 : (z == 1) ? b1 : b2;
    float* C = (z == 0) ? C0 : (z == 1) ? C1 : C2;
    gemm_core(A, W, b, C, blockIdx.y * BM, blockIdx.x * BN);
}

// ---------------------------------------------------------------------------
// GEMM (BM=64, for Wo): 384 CTAs -> ~1 full wave instead of 0.65.
// ---------------------------------------------------------------------------
#define BM2 64
#define GEMM_SMEM2 ((2 * BM2 * GAST + 2 * GBK * GBST) * 4)

__global__ __launch_bounds__(256) void gemm_m64_kernel(
    const float* __restrict__ A, const float* __restrict__ W,
    const float* __restrict__ bias, float* __restrict__ C) {
    extern __shared__ float gsm[];
    float* AsF = gsm;
    float* BsF = gsm + 2 * BM2 * GAST;

    const int tid = threadIdx.x;
    const int wid = tid >> 5;
    const int lane = tid & 31;
    const int g = lane >> 2;
    const int tg = lane & 3;
    const int wm = (wid & 1) * 32;   // 2 m-tiles of 16
    const int wn = (wid >> 1) * 32;
    const int m0 = blockIdx.y * BM2;
    const int n0 = blockIdx.x * BN;

    const uint32_t sA0 = smem_u32(AsF);
    const uint32_t sA1 = smem_u32(AsF + BM2 * GAST);
    const uint32_t sB0 = smem_u32(BsF);
    const uint32_t sB1 = smem_u32(BsF + GBK * GBST);

    float acc[2][4][4] = {};

    auto load_tile = [&](int ki, int st) {
        uint32_t sa = st ? sA1 : sA0;
        uint32_t sb = st ? sB1 : sB0;
        const int k0 = ki * GBK;
        #pragma unroll
        for (int j = 0; j < 2; ++j) {     // A: 64x32 = 512 float4 slots
            int s = tid + j * 256;
            int ra = s >> 3, ca = (s & 7) * 4;
            cp_async16(sa + (ra * GAST + ca) * 4,
                       &A[(size_t)(m0 + ra) * DM + k0 + ca]);
        }
        #pragma unroll
        for (int j = 0; j < 4; ++j) {     // B: 32x128 = 1024 float4 slots
            int s = tid + j * 256;
            int rb = s >> 5, cb = (s & 31) * 4;
            cp_async16(sb + (rb * GBST + cb) * 4,
                       &W[(size_t)(k0 + rb) * DM + n0 + cb]);
        }
        cp_commit();
    };

    load_tile(0, 0);

    const int NIT = DM / GBK;  // 24
    for (int ki = 0; ki < NIT; ++ki) {
        const int st = ki & 1;
        cp_wait<0>();
        __syncthreads();
        if (ki + 1 < NIT) load_tile(ki + 1, st ^ 1);

        const float* Af = AsF + st * BM2 * GAST;
        const float* Bf = BsF + st * GBK * GBST;

        #pragma unroll
        for (int ks = 0; ks < GBK; ks += 8) {
            uint32_t af[2][4], bfh[4][2], bfl[4][2];
            #pragma unroll
            for (int mt = 0; mt < 2; ++mt) {
                int rb = wm + mt * 16;
                af[mt][0] = f2tf32(Af[(rb + g) * GAST + ks + tg]);
                af[mt][1] = f2tf32(Af[(rb + g + 8) * GAST + ks + tg]);
                af[mt][2] = f2tf32(Af[(rb + g) * GAST + ks + tg + 4]);
                af[mt][3] = f2tf32(Af[(rb + g + 8) * GAST + ks + tg + 4]);
            }
            #pragma unroll
            for (int nt = 0; nt < 4; ++nt) {
                int cb = wn + nt * 8;
                float b0 = Bf[(ks + tg) * GBST + cb + g];
                float b1 = Bf[(ks + tg + 4) * GBST + cb + g];
                bfh[nt][0] = f2tf32(b0);
                bfh[nt][1] = f2tf32(b1);
                bfl[nt][0] = f2tf32(b0 - __uint_as_float(bfh[nt][0]));
                bfl[nt][1] = f2tf32(b1 - __uint_as_float(bfh[nt][1]));
            }
            #pragma unroll
            for (int mt = 0; mt < 2; ++mt)
                #pragma unroll
                for (int nt = 0; nt < 4; ++nt)
                    mma_tf32(acc[mt][nt], af[mt], bfl[nt]);
            #pragma unroll
            for (int mt = 0; mt < 2; ++mt)
                #pragma unroll
                for (int nt = 0; nt < 4; ++nt)
                    mma_tf32(acc[mt][nt], af[mt], bfh[nt]);
        }
    }

    #pragma unroll
    for (int mt = 0; mt < 2; ++mt) {
        int row = m0 + wm + mt * 16 + g;
        #pragma unroll
        for (int nt = 0; nt < 4; ++nt) {
            int col = n0 + wn + nt * 8 + tg * 2;
            float b0 = bias[col], b1 = bias[col + 1];
            float2 v0 = make_float2(acc[mt][nt][0] + b0, acc[mt][nt][1] + b1);
            float2 v1 = make_float2(acc[mt][nt][2] + b0, acc[mt][nt][3] + b1);
            *reinterpret_cast<float2*>(&C[(size_t)row * DM + col]) = v0;
            *reinterpret_cast<float2*>(&C[(size_t)(row + 8) * DM + col]) = v1;
        }
    }
}

// ---------------------------------------------------------------------------
// Tensorized causal flash attention, SPLIT-KV, with PAIR-PACKED K/V smem:
// B-fragments load as one LDS.64 instead of two LDS.32.
//   Kp: [64 rows][72 words]; group kc: words kc*8+2t   = K[r][kc*8+t],
//                                       words kc*8+2t+1 = K[r][kc*8+t+4]
//   Vp: [32 pair-rows][144 words]; pair-row pr=(kc,tg): word 2c = V[kc*8+tg][c],
//                                       word 2c+1 = V[kc*8+tg+4][c]
// Read banks: K: 8g+2tg -> each bank 2x (optimal for .64); V: 16tg+2g same.
// ---------------------------------------------------------------------------
#define KSTP 72
#define VSTP 144
#define PST 68
#define ATTN_SMEM ((64 * KSTP + 32 * VSTP + 128 * PST) * 4)

__global__ __launch_bounds__(256) void attn_mma_kernel() {
    extern __shared__ uint32_t smu[];
    uint32_t* Kp = smu;                         // [64][KSTP]
    uint32_t* Vp = Kp + 64 * KSTP;              // [32][VSTP]
    uint32_t* Ps = Vp + 32 * VSTP;              // [128][PST]

    const int uid = blockIdx.x;
    const int h = blockIdx.y;
    int qb, t_begin, t_end, half;
    bool split;
    if (uid < 32) {
        qb = 31 - (uid >> 1);
        half = uid & 1;
        split = true;
        if (half == 0) { t_begin = 0;      t_end = qb + 1; }
        else           { t_begin = qb + 1; t_end = 2 * qb + 2; }
    } else {
        qb = 47 - uid;
        half = 0;
        split = false;
        t_begin = 0;
        t_end = 2 * qb + 2;
    }

    const int tid = threadIdx.x;
    const int w = tid >> 5;
    const int lane = tid & 31;
    const int g = lane >> 2;
    const int tg = lane & 3;
    const int r0g = qb * 128 + w * 16 + g;

    // Stage Q (scaled, tf32) into Ps; gather A-fragments into registers.
    #pragma unroll 2
    for (int i = tid; i < 128 * 16; i += 256) {
        int r = i >> 4, cq = (i & 15) * 4;
        float4 v = *reinterpret_cast<const float4*>(
            &g_Q[(size_t)(qb * 128 + r) * DM + h * DK + cq]);
        uint32_t* p = &Ps[r * PST + cq];
        p[0] = f2tf32(v.x * 0.125f);
        p[1] = f2tf32(v.y * 0.125f);
        p[2] = f2tf32(v.z * 0.125f);
        p[3] = f2tf32(v.w * 0.125f);
    }
    __syncthreads();

    uint32_t qa[8][4];
    #pragma unroll
    for (int kc = 0; kc < 8; ++kc) {
        qa[kc][0] = Ps[(w * 16 + g) * PST + kc * 8 + tg];
        qa[kc][1] = Ps[(w * 16 + g + 8) * PST + kc * 8 + tg];
        qa[kc][2] = Ps[(w * 16 + g) * PST + kc * 8 + tg + 4];
        qa[kc][3] = Ps[(w * 16 + g + 8) * PST + kc * 8 + tg + 4];
    }

    float m0 = -1e30f, m1 = -1e30f, l0 = 0.0f, l1 = 0.0f;
    float o[8][4] = {};

    for (int t = t_begin; t < t_end; ++t) {
        __syncthreads();
        // Stage K (pair-packed along columns) and V (pair-packed along rows).
        #pragma unroll
        for (int j = 0; j < 2; ++j) {
            int i = tid + j * 256;
            // K task: row r, column group kc (8 cols).
            {
                int r = i >> 3, kc = i & 7;
                size_t gb = (size_t)(t * 64 + r) * DM + h * DK + kc * 8;
                float4 f0 = *reinterpret_cast<const float4*>(&g_K[gb]);
                float4 f1 = *reinterpret_cast<const float4*>(&g_K[gb + 4]);
                uint32_t* pk = &Kp[r * KSTP + kc * 8];
                uint4 w0, w1;
                w0.x = f2tf32(f0.x); w0.y = f2tf32(f1.x);
                w0.z = f2tf32(f0.y); w0.w = f2tf32(f1.y);
                w1.x = f2tf32(f0.z); w1.y = f2tf32(f1.z);
                w1.z = f2tf32(f0.w); w1.w = f2tf32(f1.w);
                *reinterpret_cast<uint4*>(pk) = w0;
                *reinterpret_cast<uint4*>(pk + 4) = w1;
            }
            // V task: pair-row pr (rows R0, R0+4), 4 columns.
            {
                int pr = i >> 4, cq = (i & 15) * 4;
                int R0 = (pr >> 2) * 8 + (pr & 3);
                size_t gv = (size_t)(t * 64 + R0) * DM + h * DK + cq;
                float4 v0 = *reinterpret_cast<const float4*>(&g_V[gv]);
                float4 v1 = *reinterpret_cast<const float4*>(&g_V[gv + 4 * DM]);
                uint32_t* pv = &Vp[pr * VSTP + cq * 2];
                uint4 u0, u1;
                u0.x = f2tf32(v0.x); u0.y = f2tf32(v1.x);
                u0.z = f2tf32(v0.y); u0.w = f2tf32(v1.y);
                u1.x = f2tf32(v0.z); u1.y = f2tf32(v1.z);
                u1.z = f2tf32(v0.w); u1.w = f2tf32(v1.w);
                *reinterpret_cast<uint4*>(pv) = u0;
                *reinterpret_cast<uint4*>(pv + 4) = u1;
            }
        }
        __syncthreads();

        const bool warp_active = (t * 64 <= qb * 128 + w * 16 + 15);
        if (!warp_active) continue;

        // S = Q K^T  (B-fragments: one LDS.64 per nt)
        float sa[8][4] = {};
        #pragma unroll
        for (int kc = 0; kc < 8; ++kc) {
            uint32_t bf[8][2];
            #pragma unroll
            for (int nt = 0; nt < 8; ++nt) {
                uint2 kb = *reinterpret_cast<const uint2*>(
                    &Kp[(nt * 8 + g) * KSTP + kc * 8 + tg * 2]);
                bf[nt][0] = kb.x;
                bf[nt][1] = kb.y;
            }
            #pragma unroll
            for (int nt = 0; nt < 8; ++nt)
                mma_tf32(sa[nt], qa[kc], bf[nt]);
        }

        // Causal mask (only diagonal-overlapping tiles; never hits in half A)
        if (t >= 2 * qb) {
            #pragma unroll
            for (int nt = 0; nt < 8; ++nt) {
                int c0 = t * 64 + nt * 8 + 2 * tg;
                if (c0 > r0g)         sa[nt][0] = -1e30f;
                if (c0 + 1 > r0g)     sa[nt][1] = -1e30f;
                if (c0 > r0g + 8)     sa[nt][2] = -1e30f;
                if (c0 + 1 > r0g + 8) sa[nt][3] = -1e30f;
            }
        }

        // Online softmax (rows g, g+8; quad reduction)
        float smax0 = -1e30f, smax1 = -1e30f;
        #pragma unroll
        for (int nt = 0; nt < 8; ++nt) {
            smax0 = fmaxf(smax0, fmaxf(sa[nt][0], sa[nt][1]));
            smax1 = fmaxf(smax1, fmaxf(sa[nt][2], sa[nt][3]));
        }
        smax0 = fmaxf(smax0, __shfl_xor_sync(0xffffffffu, smax0, 1));
        smax0 = fmaxf(smax0, __shfl_xor_sync(0xffffffffu, smax0, 2));
        smax1 = fmaxf(smax1, __shfl_xor_sync(0xffffffffu, smax1, 1));
        smax1 = fmaxf(smax1, __shfl_xor_sync(0xffffffffu, smax1, 2));

        float mn0 = fmaxf(m0, smax0);
        float mn1 = fmaxf(m1, smax1);
        float corr0 = __expf(m0 - mn0);
        float corr1 = __expf(m1 - mn1);
        float rs0 = 0.0f, rs1 = 0.0f;
        #pragma unroll
        for (int nt = 0; nt < 8; ++nt) {
            sa[nt][0] = __expf(sa[nt][0] - mn0);
            sa[nt][1] = __expf(sa[nt][1] - mn0);
            sa[nt][2] = __expf(sa[nt][2] - mn1);
            sa[nt][3] = __expf(sa[nt][3] - mn1);
            rs0 += sa[nt][0] + sa[nt][1];
            rs1 += sa[nt][2] + sa[nt][3];
        }
        rs0 += __shfl_xor_sync(0xffffffffu, rs0, 1);
        rs0 += __shfl_xor_sync(0xffffffffu, rs0, 2);
        rs1 += __shfl_xor_sync(0xffffffffu, rs1, 1);
        rs1 += __shfl_xor_sync(0xffffffffu, rs1, 2);

        l0 = l0 * corr0 + rs0;  m0 = mn0;
        l1 = l1 * corr1 + rs1;  m1 = mn1;
        #pragma unroll
        for (int nt = 0; nt < 8; ++nt) {
            o[nt][0] *= corr0;  o[nt][1] *= corr0;
            o[nt][2] *= corr1;  o[nt][3] *= corr1;
        }

        // P -> Ps (warp-private rows), warp-sync only.
        #pragma unroll
        for (int nt = 0; nt < 8; ++nt) {
            int c = nt * 8 + 2 * tg;
            uint2 p0 = make_uint2(f2tf32(sa[nt][0]), f2tf32(sa[nt][1]));
            uint2 p1 = make_uint2(f2tf32(sa[nt][2]), f2tf32(sa[nt][3]));
            *reinterpret_cast<uint2*>(&Ps[(w * 16 + g) * PST + c]) = p0;
            *reinterpret_cast<uint2*>(&Ps[(w * 16 + g + 8) * PST + c]) = p1;
        }
        __syncwarp();

        // O += P V  (B-fragments: one LDS.64 per nt)
        #pragma unroll
        for (int kc = 0; kc < 8; ++kc) {
            uint32_t pa[4];
            pa[0] = Ps[(w * 16 + g) * PST + kc * 8 + tg];
            pa[1] = Ps[(w * 16 + g + 8) * PST + kc * 8 + tg];
            pa[2] = Ps[(w * 16 + g) * PST + kc * 8 + tg + 4];
            pa[3] = Ps[(w * 16 + g + 8) * PST + kc * 8 + tg + 4];
            uint32_t bf[8][2];
            #pragma unroll
            for (int nt = 0; nt < 8; ++nt) {
                uint2 vb = *reinterpret_cast<const uint2*>(
                    &Vp[(kc * 4 + tg) * VSTP + nt * 16 + g * 2]);
                bf[nt][0] = vb.x;
                bf[nt][1] = vb.y;
            }
            #pragma unroll
            for (int nt = 0; nt < 8; ++nt)
                mma_tf32(o[nt], pa, bf[nt]);
        }
    }

    if (!split) {
        float inv0 = 1.0f / l0;
        float inv1 = 1.0f / l1;
        #pragma unroll
        for (int nt = 0; nt < 8; ++nt) {
            int col = h * DK + nt * 8 + 2 * tg;
            float2 v0 = make_float2(o[nt][0] * inv0, o[nt][1] * inv0);
            float2 v1 = make_float2(o[nt][2] * inv1, o[nt][3] * inv1);
            *reinterpret_cast<float2*>(&g_C[(size_t)r0g * DM + col]) = v0;
            *reinterpret_cast<float2*>(&g_C[(size_t)(r0g + 8) * DM + col]) = v1;
        }
    } else {
        float* P = half ? g_PB : g_PA;
        float* M = half ? g_MB : g_MA;
        float* L = half ? g_LB : g_LA;
        #pragma unroll
        for (int nt = 0; nt < 8; ++nt) {
            int col = h * DK + nt * 8 + 2 * tg;
            float2 v0 = make_float2(o[nt][0], o[nt][1]);
            float2 v1 = make_float2(o[nt][2], o[nt][3]);
            *reinterpret_cast<float2*>(&P[(size_t)r0g * DM + col]) = v0;
            *reinterpret_cast<float2*>(&P[(size_t)(r0g + 8) * DM + col]) = v1;
        }
        if (tg == 0) {
            M[h * SMAX + r0g] = m0;       L[h * SMAX + r0g] = l0;
            M[h * SMAX + r0g + 8] = m1;   L[h * SMAX + r0g + 8] = l1;
        }
    }
}

// ---------------------------------------------------------------------------
// Combine: merge the two split-KV partials for rows [S/2, S).
// ---------------------------------------------------------------------------
__global__ __launch_bounds__(256) void attn_combine_kernel(int S) {
    const int idx = blockIdx.x * 256 + threadIdx.x;
    const int f4_per_row = DM / 4;                 // 192
    const int row = S / 2 + idx / f4_per_row;
    const int c4 = (idx % f4_per_row) * 4;
    const int h = c4 / DK;

    const float mA = g_MA[h * SMAX + row];
    const float lA = g_LA[h * SMAX + row];
    const float mB = g_MB[h * SMAX + row];
    const float lB = g_LB[h * SMAX + row];
    const float m = fmaxf(mA, mB);
    const float sA = __expf(mA - m);
    const float sB = __expf(mB - m);
    const float inv = 1.0f / (lA * sA + lB * sB);

    const size_t off = (size_t)row * DM + c4;
    float4 oA = *reinterpret_cast<const float4*>(&g_PA[off]);
    float4 oB = *reinterpret_cast<const float4*>(&g_PB[off]);
    float4 out;
    out.x = (oA.x * sA + oB.x * sB) * inv;
    out.y = (oA.y * sA + oB.y * sB) * inv;
    out.z = (oA.z * sA + oB.z * sB) * inv;
    out.w = (oA.w * sA + oB.w * sB) * inv;
    *reinterpret_cast<float4*>(&g_C[off]) = out;
}

// ---------------------------------------------------------------------------
// Launch
// ---------------------------------------------------------------------------
extern "C" void kernel_launch(void* const* d_in, const int* in_sizes, int n_in,
                              void* d_out, int out_size) {
    const float* q  = (const float*)d_in[0];
    const float* k  = (const float*)d_in[1];
    const float* v  = (const float*)d_in[2];
    // d_in[3] = mask (tril, enforced analytically)
    const float* Wq = (const float*)d_in[4];
    const float* bq = (const float*)d_in[5];
    const float* Wk = (const float*)d_in[6];
    const float* bk = (const float*)d_in[7];
    const float* Wv = (const float*)d_in[8];
    const float* bv = (const float*)d_in[9];
    const float* Wo = (const float*)d_in[10];
    const float* bo = (const float*)d_in[11];
    float* out = (float*)d_out;

    const int S = in_sizes[0] / DM;   // 4096

    float *pQ, *pK, *pV, *pC;
    cudaGetSymbolAddress((void**)&pQ, g_Q);
    cudaGetSymbolAddress((void**)&pK, g_K);
    cudaGetSymbolAddress((void**)&pV, g_V);
    cudaGetSymbolAddress((void**)&pC, g_C);

    cudaFuncSetAttribute(gemm_qkv_kernel,
                         cudaFuncAttributeMaxDynamicSharedMemorySize, GEMM_SMEM);
    cudaFuncSetAttribute(gemm_m64_kernel,
                         cudaFuncAttributeMaxDynamicSharedMemorySize, GEMM_SMEM2);
    cudaFuncSetAttribute(attn_mma_kernel,
                         cudaFuncAttributeMaxDynamicSharedMemorySize, ATTN_SMEM);

    dim3 qkvgrid(DM / BN, S / BM, 3);   // (6, 32, 3)
    gemm_qkv_kernel<<<qkvgrid, 256, GEMM_SMEM>>>(q, k, v, Wq, Wk, Wv,
                                                 bq, bk, bv, pQ, pK, pV);

    // 48 units per head: 32 split halves (qb 16..31) + 16 full (qb 0..15)
    attn_mma_kernel<<<dim3(48, NH), 256, ATTN_SMEM>>>();

    // Merge partials for rows [S/2, S)
    const int combine_blocks = (S / 2) * (DM / 4) / 256;   // 1536
    attn_combine_kernel<<<combine_blocks, 256>>>(S);

    dim3 wogrid(DM / BN, S / BM2);      // (6, 64)
    gemm_m64_kernel<<<wogrid, 256, GEMM_SMEM2>>>(pC, Wo, bo, out);
}

// round 16
// speedup vs baseline: 1.1078x; 1.1078x over previous
#include <cuda_runtime.h>
#include <math.h>
#include <stdint.h>

#define DM 768
#define NH 12
#define DK 64
#define SMAX 4096

__device__ float g_Q[SMAX * DM];
__device__ float g_K[SMAX * DM];
__device__ float g_V[SMAX * DM];
__device__ float g_C[SMAX * DM];
// Split-KV partial buffers (half A / half B), rows >= SMAX/2 used.
__device__ float g_PA[SMAX * DM];
__device__ float g_PB[SMAX * DM];
__device__ float g_MA[NH * SMAX], g_LA[NH * SMAX];
__device__ float g_MB[NH * SMAX], g_LB[NH * SMAX];

__device__ __forceinline__ uint32_t f2tf32(float f) {
    uint32_t r;
    asm("cvt.rna.tf32.f32 %0, %1;" : "=r"(r) : "f"(f));
    return r;
}

__device__ __forceinline__ uint32_t smem_u32(const void* p) {
    uint32_t a;
    asm("{ .reg .u64 t; cvta.to.shared.u64 t, %1; cvt.u32.u64 %0, t; }"
        : "=r"(a) : "l"(p));
    return a;
}

__device__ __forceinline__ void cp_async16(uint32_t smem_addr, const void* gptr) {
    asm volatile("cp.async.ca.shared.global [%0], [%1], 16;"
                 :: "r"(smem_addr), "l"(gptr));
}
__device__ __forceinline__ void cp_commit() {
    asm volatile("cp.async.commit_group;");
}
template <int N>
__device__ __forceinline__ void cp_wait() {
    asm volatile("cp.async.wait_group %0;" :: "n"(N));
}

__device__ __forceinline__ void mma_tf32(float* d, const uint32_t* a, const uint32_t* b) {
    asm volatile(
        "mma.sync.aligned.m16n8k8.row.col.f32.tf32.tf32.f32 "
        "{%0,%1,%2,%3}, {%4,%5,%6,%7}, {%8,%9}, {%0,%1,%2,%3};"
        : "+f"(d[0]), "+f"(d[1]), "+f"(d[2]), "+f"(d[3])
        : "r"(a[0]), "r"(a[1]), "r"(a[2]), "r"(a[3]), "r"(b[0]), "r"(b[1]));
}

// ---------------------------------------------------------------------------
// GEMM (BM=128, for QKV): 2x-tf32, BK=32, cp.async double buffer.
// ---------------------------------------------------------------------------
#define BM 128
#define BN 128
#define GBK 32
#define GAST 36
#define GBST 136
#define GEMM_SMEM ((2 * BM * GAST + 2 * GBK * GBST) * 4)

__device__ __forceinline__ void gemm_core(
    const float* __restrict__ A, const float* __restrict__ W,
    const float* __restrict__ bias, float* __restrict__ C,
    int m0, int n0) {
    extern __shared__ float gsm[];
    float* AsF = gsm;
    float* BsF = gsm + 2 * BM * GAST;

    const int tid = threadIdx.x;
    const int wid = tid >> 5;
    const int lane = tid & 31;
    const int g = lane >> 2;
    const int tg = lane & 3;
    const int wm = (wid & 1) * 64;
    const int wn = (wid >> 1) * 32;

    const uint32_t sA0 = smem_u32(AsF);
    const uint32_t sA1 = smem_u32(AsF + BM * GAST);
    const uint32_t sB0 = smem_u32(BsF);
    const uint32_t sB1 = smem_u32(BsF + GBK * GBST);

    float acc[4][4][4] = {};

    auto load_tile = [&](int ki, int st) {
        uint32_t sa = st ? sA1 : sA0;
        uint32_t sb = st ? sB1 : sB0;
        const int k0 = ki * GBK;
        #pragma unroll
        for (int j = 0; j < 4; ++j) {
            int s = tid + j * 256;
            int ra = s >> 3, ca = (s & 7) * 4;
            cp_async16(sa + (ra * GAST + ca) * 4,
                       &A[(size_t)(m0 + ra) * DM + k0 + ca]);
        }
        #pragma unroll
        for (int j = 0; j < 4; ++j) {
            int s = tid + j * 256;
            int rb = s >> 5, cb = (s & 31) * 4;
            cp_async16(sb + (rb * GBST + cb) * 4,
                       &W[(size_t)(k0 + rb) * DM + n0 + cb]);
        }
        cp_commit();
    };

    load_tile(0, 0);

    const int NIT = DM / GBK;  // 24
    for (int ki = 0; ki < NIT; ++ki) {
        const int st = ki & 1;
        cp_wait<0>();
        __syncthreads();
        if (ki + 1 < NIT) load_tile(ki + 1, st ^ 1);

        const float* Af = AsF + st * BM * GAST;
        const float* Bf = BsF + st * GBK * GBST;

        #pragma unroll
        for (int ks = 0; ks < GBK; ks += 8) {
            uint32_t af[4][4], bfh[4][2], bfl[4][2];
            #pragma unroll
            for (int mt = 0; mt < 4; ++mt) {
                int rb = wm + mt * 16;
                af[mt][0] = f2tf32(Af[(rb + g) * GAST + ks + tg]);
                af[mt][1] = f2tf32(Af[(rb + g + 8) * GAST + ks + tg]);
                af[mt][2] = f2tf32(Af[(rb + g) * GAST + ks + tg + 4]);
                af[mt][3] = f2tf32(Af[(rb + g + 8) * GAST + ks + tg + 4]);
            }
            #pragma unroll
            for (int nt = 0; nt < 4; ++nt) {
                int cb = wn + nt * 8;
                float b0 = Bf[(ks + tg) * GBST + cb + g];
                float b1 = Bf[(ks + tg + 4) * GBST + cb + g];
                bfh[nt][0] = f2tf32(b0);
                bfh[nt][1] = f2tf32(b1);
                bfl[nt][0] = f2tf32(b0 - __uint_as_float(bfh[nt][0]));
                bfl[nt][1] = f2tf32(b1 - __uint_as_float(bfh[nt][1]));
            }
            #pragma unroll
            for (int mt = 0; mt < 4; ++mt)
                #pragma unroll
                for (int nt = 0; nt < 4; ++nt)
                    mma_tf32(acc[mt][nt], af[mt], bfl[nt]);
            #pragma unroll
            for (int mt = 0; mt < 4; ++mt)
                #pragma unroll
                for (int nt = 0; nt < 4; ++nt)
                    mma_tf32(acc[mt][nt], af[mt], bfh[nt]);
        }
    }

    #pragma unroll
    for (int mt = 0; mt < 4; ++mt) {
        int row = m0 + wm + mt * 16 + g;
        #pragma unroll
        for (int nt = 0; nt < 4; ++nt) {
            int col = n0 + wn + nt * 8 + tg * 2;
            float b0 = bias[col], b1 = bias[col + 1];
            float2 v0 = make_float2(acc[mt][nt][0] + b0, acc[mt][nt][1] + b1);
            float2 v1 = make_float2(acc[mt][nt][2] + b0, acc[mt][nt][3] + b1);
            *reinterpret_cast<float2*>(&C[(size_t)row * DM + col]) = v0;
            *reinterpret_cast<float2*>(&C[(size_t)(row + 8) * DM + col]) = v1;
        }
    }
}

__global__ __launch_bounds__(256) void gemm_qkv_kernel(
    const float* A0, const float* A1, const float* A2,
    const float* W0, const float* W1, const float* W2,
    const float* b0, const float* b1, const float* b2,
    float* C0, float* C1, float* C2) {
    const int z = blockIdx.z;
    const float* A = (z == 0) ? A0 : (z == 1) ? A1 : A2;
    const float* W = (z == 0) ? W0 : (z == 1) ? W1 : W2;
    const float* b = (z == 0) ? b0 : (z == 1) ? b1 : b2;
    float* C = (z == 0) ? C0 : (z == 1) ? C1 : C2;
    gemm_core(A, W, b, C, blockIdx.y * BM, blockIdx.x * BN);
}

// ---------------------------------------------------------------------------
// GEMM (BM=64, for Wo): 384 CTAs, measured 76.5us (win vs 86.6 at BM=128).
// ---------------------------------------------------------------------------
#define BM2 64
#define GEMM_SMEM2 ((2 * BM2 * GAST + 2 * GBK * GBST) * 4)

__global__ __launch_bounds__(256) void gemm_m64_kernel(
    const float* __restrict__ A, const float* __restrict__ W,
    const float* __restrict__ bias, float* __restrict__ C) {
    extern __shared__ float gsm[];
    float* AsF = gsm;
    float* BsF = gsm + 2 * BM2 * GAST;

    const int tid = threadIdx.x;
    const int wid = tid >> 5;
    const int lane = tid & 31;
    const int g = lane >> 2;
    const int tg = lane & 3;
    const int wm = (wid & 1) * 32;   // 2 m-tiles of 16
    const int wn = (wid >> 1) * 32;
    const int m0 = blockIdx.y * BM2;
    const int n0 = blockIdx.x * BN;

    const uint32_t sA0 = smem_u32(AsF);
    const uint32_t sA1 = smem_u32(AsF + BM2 * GAST);
    const uint32_t sB0 = smem_u32(BsF);
    const uint32_t sB1 = smem_u32(BsF + GBK * GBST);

    float acc[2][4][4] = {};

    auto load_tile = [&](int ki, int st) {
        uint32_t sa = st ? sA1 : sA0;
        uint32_t sb = st ? sB1 : sB0;
        const int k0 = ki * GBK;
        #pragma unroll
        for (int j = 0; j < 2; ++j) {     // A: 64x32 = 512 float4 slots
            int s = tid + j * 256;
            int ra = s >> 3, ca = (s & 7) * 4;
            cp_async16(sa + (ra * GAST + ca) * 4,
                       &A[(size_t)(m0 + ra) * DM + k0 + ca]);
        }
        #pragma unroll
        for (int j = 0; j < 4; ++j) {     // B: 32x128 = 1024 float4 slots
            int s = tid + j * 256;
            int rb = s >> 5, cb = (s & 31) * 4;
            cp_async16(sb + (rb * GBST + cb) * 4,
                       &W[(size_t)(k0 + rb) * DM + n0 + cb]);
        }
        cp_commit();
    };

    load_tile(0, 0);

    const int NIT = DM / GBK;  // 24
    for (int ki = 0; ki < NIT; ++ki) {
        const int st = ki & 1;
        cp_wait<0>();
        __syncthreads();
        if (ki + 1 < NIT) load_tile(ki + 1, st ^ 1);

        const float* Af = AsF + st * BM2 * GAST;
        const float* Bf = BsF + st * GBK * GBST;

        #pragma unroll
        for (int ks = 0; ks < GBK; ks += 8) {
            uint32_t af[2][4], bfh[4][2], bfl[4][2];
            #pragma unroll
            for (int mt = 0; mt < 2; ++mt) {
                int rb = wm + mt * 16;
                af[mt][0] = f2tf32(Af[(rb + g) * GAST + ks + tg]);
                af[mt][1] = f2tf32(Af[(rb + g + 8) * GAST + ks + tg]);
                af[mt][2] = f2tf32(Af[(rb + g) * GAST + ks + tg + 4]);
                af[mt][3] = f2tf32(Af[(rb + g + 8) * GAST + ks + tg + 4]);
            }
            #pragma unroll
            for (int nt = 0; nt < 4; ++nt) {
                int cb = wn + nt * 8;
                float b0 = Bf[(ks + tg) * GBST + cb + g];
                float b1 = Bf[(ks + tg + 4) * GBST + cb + g];
                bfh[nt][0] = f2tf32(b0);
                bfh[nt][1] = f2tf32(b1);
                bfl[nt][0] = f2tf32(b0 - __uint_as_float(bfh[nt][0]));
                bfl[nt][1] = f2tf32(b1 - __uint_as_float(bfh[nt][1]));
            }
            #pragma unroll
            for (int mt = 0; mt < 2; ++mt)
                #pragma unroll
                for (int nt = 0; nt < 4; ++nt)
                    mma_tf32(acc[mt][nt], af[mt], bfl[nt]);
            #pragma unroll
            for (int mt = 0; mt < 2; ++mt)
                #pragma unroll
                for (int nt = 0; nt < 4; ++nt)
                    mma_tf32(acc[mt][nt], af[mt], bfh[nt]);
        }
    }

    #pragma unroll
    for (int mt = 0; mt < 2; ++mt) {
        int row = m0 + wm + mt * 16 + g;
        #pragma unroll
        for (int nt = 0; nt < 4; ++nt) {
            int col = n0 + wn + nt * 8 + tg * 2;
            float b0 = bias[col], b1 = bias[col + 1];
            float2 v0 = make_float2(acc[mt][nt][0] + b0, acc[mt][nt][1] + b1);
            float2 v1 = make_float2(acc[mt][nt][2] + b0, acc[mt][nt][3] + b1);
            *reinterpret_cast<float2*>(&C[(size_t)row * DM + col]) = v0;
            *reinterpret_cast<float2*>(&C[(size_t)(row + 8) * DM + col]) = v1;
        }
    }
}

// ---------------------------------------------------------------------------
// Tensorized causal flash attention, SPLIT-KV (R11 version — measured best):
// single-buffered K/V, convert-once at load, LDS.32 fragment gathers.
// ---------------------------------------------------------------------------
#define KST 68   // K row stride: banks (4g+tg) distinct for B-frag gather
#define VST 72   // V row stride: banks (8tg+g) distinct
#define PST 68   // P/Q row stride: banks (4g+tg) distinct for A-frag gather
#define ATTN_SMEM ((64 * KST + 64 * VST + 128 * PST) * 4)

__global__ __launch_bounds__(256) void attn_mma_kernel() {
    extern __shared__ uint32_t smu[];
    uint32_t* Ks = smu;                    // [64][KST]
    uint32_t* Vs = Ks + 64 * KST;          // [64][VST]
    uint32_t* Ps = Vs + 64 * VST;          // [128][PST]

    const int uid = blockIdx.x;
    const int h = blockIdx.y;
    int qb, t_begin, t_end, half;
    bool split;
    if (uid < 32) {
        qb = 31 - (uid >> 1);
        half = uid & 1;
        split = true;
        if (half == 0) { t_begin = 0;      t_end = qb + 1; }
        else           { t_begin = qb + 1; t_end = 2 * qb + 2; }
    } else {
        qb = 47 - uid;
        half = 0;
        split = false;
        t_begin = 0;
        t_end = 2 * qb + 2;
    }

    const int tid = threadIdx.x;
    const int w = tid >> 5;
    const int lane = tid & 31;
    const int g = lane >> 2;
    const int tg = lane & 3;
    const int r0g = qb * 128 + w * 16 + g;

    // Stage Q (scaled, tf32) into Ps; gather A-fragments into registers.
    #pragma unroll 2
    for (int i = tid; i < 128 * 16; i += 256) {
        int r = i >> 4, cq = (i & 15) * 4;
        float4 v = *reinterpret_cast<const float4*>(
            &g_Q[(size_t)(qb * 128 + r) * DM + h * DK + cq]);
        uint32_t* p = &Ps[r * PST + cq];
        p[0] = f2tf32(v.x * 0.125f);
        p[1] = f2tf32(v.y * 0.125f);
        p[2] = f2tf32(v.z * 0.125f);
        p[3] = f2tf32(v.w * 0.125f);
    }
    __syncthreads();

    uint32_t qa[8][4];
    #pragma unroll
    for (int kc = 0; kc < 8; ++kc) {   // warp-private rows of Ps
        qa[kc][0] = Ps[(w * 16 + g) * PST + kc * 8 + tg];
        qa[kc][1] = Ps[(w * 16 + g + 8) * PST + kc * 8 + tg];
        qa[kc][2] = Ps[(w * 16 + g) * PST + kc * 8 + tg + 4];
        qa[kc][3] = Ps[(w * 16 + g + 8) * PST + kc * 8 + tg + 4];
    }

    float m0 = -1e30f, m1 = -1e30f, l0 = 0.0f, l1 = 0.0f;
    float o[8][4] = {};

    for (int t = t_begin; t < t_end; ++t) {
        __syncthreads();
        #pragma unroll
        for (int j = 0; j < 4; ++j) {
            int i = tid + j * 256;
            int r = i >> 4, cq = (i & 15) * 4;
            size_t gk = (size_t)(t * 64 + r) * DM + h * DK + cq;
            float4 kv = *reinterpret_cast<const float4*>(&g_K[gk]);
            float4 vv = *reinterpret_cast<const float4*>(&g_V[gk]);
            uint32_t* pk = &Ks[r * KST + cq];
            pk[0] = f2tf32(kv.x); pk[1] = f2tf32(kv.y);
            pk[2] = f2tf32(kv.z); pk[3] = f2tf32(kv.w);
            uint32_t* pv = &Vs[r * VST + cq];
            pv[0] = f2tf32(vv.x); pv[1] = f2tf32(vv.y);
            pv[2] = f2tf32(vv.z); pv[3] = f2tf32(vv.w);
        }
        __syncthreads();

        const bool warp_active = (t * 64 <= qb * 128 + w * 16 + 15);
        if (!warp_active) continue;

        // S = Q K^T
        float sa[8][4] = {};
        #pragma unroll
        for (int kc = 0; kc < 8; ++kc) {
            uint32_t bf[8][2];
            #pragma unroll
            for (int nt = 0; nt < 8; ++nt) {
                bf[nt][0] = Ks[(nt * 8 + g) * KST + kc * 8 + tg];
                bf[nt][1] = Ks[(nt * 8 + g) * KST + kc * 8 + tg + 4];
            }
            #pragma unroll
            for (int nt = 0; nt < 8; ++nt)
                mma_tf32(sa[nt], qa[kc], bf[nt]);
        }

        // Causal mask (only diagonal-overlapping tiles; never hits in half A)
        if (t >= 2 * qb) {
            #pragma unroll
            for (int nt = 0; nt < 8; ++nt) {
                int c0 = t * 64 + nt * 8 + 2 * tg;
                if (c0 > r0g)         sa[nt][0] = -1e30f;
                if (c0 + 1 > r0g)     sa[nt][1] = -1e30f;
                if (c0 > r0g + 8)     sa[nt][2] = -1e30f;
                if (c0 + 1 > r0g + 8) sa[nt][3] = -1e30f;
            }
        }

        // Online softmax (rows g, g+8; quad reduction)
        float smax0 = -1e30f, smax1 = -1e30f;
        #pragma unroll
        for (int nt = 0; nt < 8; ++nt) {
            smax0 = fmaxf(smax0, fmaxf(sa[nt][0], sa[nt][1]));
            smax1 = fmaxf(smax1, fmaxf(sa[nt][2], sa[nt][3]));
        }
        smax0 = fmaxf(smax0, __shfl_xor_sync(0xffffffffu, smax0, 1));
        smax0 = fmaxf(smax0, __shfl_xor_sync(0xffffffffu, smax0, 2));
        smax1 = fmaxf(smax1, __shfl_xor_sync(0xffffffffu, smax1, 1));
        smax1 = fmaxf(smax1, __shfl_xor_sync(0xffffffffu, smax1, 2));

        float mn0 = fmaxf(m0, smax0);
        float mn1 = fmaxf(m1, smax1);
        float corr0 = __expf(m0 - mn0);
        float corr1 = __expf(m1 - mn1);
        float rs0 = 0.0f, rs1 = 0.0f;
        #pragma unroll
        for (int nt = 0; nt < 8; ++nt) {
            sa[nt][0] = __expf(sa[nt][0] - mn0);
            sa[nt][1] = __expf(sa[nt][1] - mn0);
            sa[nt][2] = __expf(sa[nt][2] - mn1);
            sa[nt][3] = __expf(sa[nt][3] - mn1);
            rs0 += sa[nt][0] + sa[nt][1];
            rs1 += sa[nt][2] + sa[nt][3];
        }
        rs0 += __shfl_xor_sync(0xffffffffu, rs0, 1);
        rs0 += __shfl_xor_sync(0xffffffffu, rs0, 2);
        rs1 += __shfl_xor_sync(0xffffffffu, rs1, 1);
        rs1 += __shfl_xor_sync(0xffffffffu, rs1, 2);

        l0 = l0 * corr0 + rs0;  m0 = mn0;
        l1 = l1 * corr1 + rs1;  m1 = mn1;
        #pragma unroll
        for (int nt = 0; nt < 8; ++nt) {
            o[nt][0] *= corr0;  o[nt][1] *= corr0;
            o[nt][2] *= corr1;  o[nt][3] *= corr1;
        }

        // P -> Ps (warp-private rows), warp-sync only.
        #pragma unroll
        for (int nt = 0; nt < 8; ++nt) {
            int c = nt * 8 + 2 * tg;
            uint2 p0 = make_uint2(f2tf32(sa[nt][0]), f2tf32(sa[nt][1]));
            uint2 p1 = make_uint2(f2tf32(sa[nt][2]), f2tf32(sa[nt][3]));
            *reinterpret_cast<uint2*>(&Ps[(w * 16 + g) * PST + c]) = p0;
            *reinterpret_cast<uint2*>(&Ps[(w * 16 + g + 8) * PST + c]) = p1;
        }
        __syncwarp();

        // O += P V
        #pragma unroll
        for (int kc = 0; kc < 8; ++kc) {
            uint32_t pa[4];
            pa[0] = Ps[(w * 16 + g) * PST + kc * 8 + tg];
            pa[1] = Ps[(w * 16 + g + 8) * PST + kc * 8 + tg];
            pa[2] = Ps[(w * 16 + g) * PST + kc * 8 + tg + 4];
            pa[3] = Ps[(w * 16 + g + 8) * PST + kc * 8 + tg + 4];
            uint32_t bf[8][2];
            #pragma unroll
            for (int nt = 0; nt < 8; ++nt) {
                bf[nt][0] = Vs[(kc * 8 + tg) * VST + nt * 8 + g];
                bf[nt][1] = Vs[(kc * 8 + tg + 4) * VST + nt * 8 + g];
            }
            #pragma unroll
            for (int nt = 0; nt < 8; ++nt)
                mma_tf32(o[nt], pa, bf[nt]);
        }
    }

    if (!split) {
        float inv0 = 1.0f / l0;
        float inv1 = 1.0f / l1;
        #pragma unroll
        for (int nt = 0; nt < 8; ++nt) {
            int col = h * DK + nt * 8 + 2 * tg;
            float2 v0 = make_float2(o[nt][0] * inv0, o[nt][1] * inv0);
            float2 v1 = make_float2(o[nt][2] * inv1, o[nt][3] * inv1);
            *reinterpret_cast<float2*>(&g_C[(size_t)r0g * DM + col]) = v0;
            *reinterpret_cast<float2*>(&g_C[(size_t)(r0g + 8) * DM + col]) = v1;
        }
    } else {
        float* P = half ? g_PB : g_PA;
        float* M = half ? g_MB : g_MA;
        float* L = half ? g_LB : g_LA;
        #pragma unroll
        for (int nt = 0; nt < 8; ++nt) {
            int col = h * DK + nt * 8 + 2 * tg;
            float2 v0 = make_float2(o[nt][0], o[nt][1]);
            float2 v1 = make_float2(o[nt][2], o[nt][3]);
            *reinterpret_cast<float2*>(&P[(size_t)r0g * DM + col]) = v0;
            *reinterpret_cast<float2*>(&P[(size_t)(r0g + 8) * DM + col]) = v1;
        }
        if (tg == 0) {
            M[h * SMAX + r0g] = m0;       L[h * SMAX + r0g] = l0;
            M[h * SMAX + r0g + 8] = m1;   L[h * SMAX + r0g + 8] = l1;
        }
    }
}

// ---------------------------------------------------------------------------
// Combine: merge the two split-KV partials for rows [S/2, S).
// ---------------------------------------------------------------------------
__global__ __launch_bounds__(256) void attn_combine_kernel(int S) {
    const int idx = blockIdx.x * 256 + threadIdx.x;
    const int f4_per_row = DM / 4;                 // 192
    const int row = S / 2 + idx / f4_per_row;
    const int c4 = (idx % f4_per_row) * 4;
    const int h = c4 / DK;

    const float mA = g_MA[h * SMAX + row];
    const float lA = g_LA[h * SMAX + row];
    const float mB = g_MB[h * SMAX + row];
    const float lB = g_LB[h * SMAX + row];
    const float m = fmaxf(mA, mB);
    const float sA = __expf(mA - m);
    const float sB = __expf(mB - m);
    const float inv = 1.0f / (lA * sA + lB * sB);

    const size_t off = (size_t)row * DM + c4;
    float4 oA = *reinterpret_cast<const float4*>(&g_PA[off]);
    float4 oB = *reinterpret_cast<const float4*>(&g_PB[off]);
    float4 out;
    out.x = (oA.x * sA + oB.x * sB) * inv;
    out.y = (oA.y * sA + oB.y * sB) * inv;
    out.z = (oA.z * sA + oB.z * sB) * inv;
    out.w = (oA.w * sA + oB.w * sB) * inv;
    *reinterpret_cast<float4*>(&g_C[off]) = out;
}

// ---------------------------------------------------------------------------
// Launch
// ---------------------------------------------------------------------------
extern "C" void kernel_launch(void* const* d_in, const int* in_sizes, int n_in,
                              void* d_out, int out_size) {
    const float* q  = (const float*)d_in[0];
    const float* k  = (const float*)d_in[1];
    const float* v  = (const float*)d_in[2];
    // d_in[3] = mask (tril, enforced analytically)
    const float* Wq = (const float*)d_in[4];
    const float* bq = (const float*)d_in[5];
    const float* Wk = (const float*)d_in[6];
    const float* bk = (const float*)d_in[7];
    const float* Wv = (const float*)d_in[8];
    const float* bv = (const float*)d_in[9];
    const float* Wo = (const float*)d_in[10];
    const float* bo = (const float*)d_in[11];
    float* out = (float*)d_out;

    const int S = in_sizes[0] / DM;   // 4096

    float *pQ, *pK, *pV, *pC;
    cudaGetSymbolAddress((void**)&pQ, g_Q);
    cudaGetSymbolAddress((void**)&pK, g_K);
    cudaGetSymbolAddress((void**)&pV, g_V);
    cudaGetSymbolAddress((void**)&pC, g_C);

    cudaFuncSetAttribute(gemm_qkv_kernel,
                         cudaFuncAttributeMaxDynamicSharedMemorySize, GEMM_SMEM);
    cudaFuncSetAttribute(gemm_m64_kernel,
                         cudaFuncAttributeMaxDynamicSharedMemorySize, GEMM_SMEM2);
    cudaFuncSetAttribute(attn_mma_kernel,
                         cudaFuncAttributeMaxDynamicSharedMemorySize, ATTN_SMEM);

    dim3 qkvgrid(DM / BN, S / BM, 3);   // (6, 32, 3)
    gemm_qkv_kernel<<<qkvgrid, 256, GEMM_SMEM>>>(q, k, v, Wq, Wk, Wv,
                                                 bq, bk, bv, pQ, pK, pV);

    // 48 units per head: 32 split halves (qb 16..31) + 16 full (qb 0..15)
    attn_mma_kernel<<<dim3(48, NH), 256, ATTN_SMEM>>>();

    // Merge partials for rows [S/2, S)
    const int combine_blocks = (S / 2) * (DM / 4) / 256;   // 1536
    attn_combine_kernel<<<combine_blocks, 256>>>(S);

    dim3 wogrid(DM / BN, S / BM2);      // (6, 64)
    gemm_m64_kernel<<<wogrid, 256, GEMM_SMEM2>>>(pC, Wo, bo, out);
}